// round 3
// baseline (speedup 1.0000x reference)
#include <cuda_runtime.h>
#include <cstdint>
#include <math.h>

// Problem constants
#define DEG 3
#define NM 32          // MU_MAX = MV_MAX
#define NU 64          // OUT_U = OUT_V
#define NBASIS 29      // mu in [4, 32]
#define BATCH 1024
#define EPSI 1e-5f

// ---------------- device globals (scratch; no allocation allowed) ----------------
__device__ float g_tab [NBASIS][NU][NM];   // basis[u][i] for each mu
__device__ float g_tabT[NBASIS][NM][NU];   // transposed: [j][v]
__device__ float g_sum [NBASIS][NU];       // row sums (partition-of-unity denom)
__device__ double g_acc_ctrl;
__device__ double g_acc_mask;
__device__ double g_acc_surf;
__device__ int    g_bad;

// knot value for clamped open-uniform vector, n_valid = mu ctrl pts, padded
__device__ __forceinline__ float kvf(int k, int mu) {
    // L = mu + DEG + 1; clamp: k <= DEG -> 0 ; k >= L-1-DEG = mu -> 1 ; else k/(L-1)
    if (k <= DEG) return 0.0f;
    if (k >= mu)  return 1.0f;
    return (float)k / (float)(mu + DEG);
}

// One block per mu value (29), one thread per u sample (64).
__global__ void build_tables_kernel() {
    int m = blockIdx.x;           // 0..28 -> mu = m+4
    int ui = threadIdx.x;         // 0..63
    if (m == 0 && ui == 0) {      // zero accumulators for this launch
        g_acc_ctrl = 0.0; g_acc_mask = 0.0; g_acc_surf = 0.0; g_bad = 0;
    }
    int mu = m + 4;
    const float step = (1.0f - 2.0f * EPSI) / 63.0f;
    float u = EPSI + step * (float)ui;

    float N[35];
#pragma unroll
    for (int k = 0; k < 35; k++) {
        float k0 = kvf(k, mu), k1 = kvf(k + 1, mu);
        N[k] = (u >= k0 && u < k1) ? 1.0f : 0.0f;
    }
#pragma unroll
    for (int d = 1; d <= DEG; d++) {
#pragma unroll
        for (int k = 0; k < 35 - 1; k++) {
            if (k >= 35 - d) break;
            float a0 = kvf(k, mu),       ad  = kvf(k + d, mu);
            float a1 = kvf(k + 1, mu),   ad1 = kvf(k + d + 1, mu);
            float den1 = ad  - a0;
            float den2 = ad1 - a1;
            float s1 = (den1 > 0.0f) ? (u - a0) / den1 : 0.0f;
            float s2 = (den2 > 0.0f) ? (ad1 - u) / den2 : 0.0f;
            N[k] = s1 * N[k] + s2 * N[k + 1];
        }
    }
    float s = 0.0f;
#pragma unroll
    for (int i = 0; i < NM; i++) {
        float v = N[i];
        g_tab [m][ui][i] = v;
        g_tabT[m][i][ui] = v;
        s += v;
    }
    g_sum[m][ui] = s;
}

// ---------------- main kernel: one block per batch sample ----------------
// smem layout (floats):
//  sBu  [64*32]   : 0     .. 2047
//  sBvT [32*64]   : 2048  .. 4095
//  sSu  [64]      : 4096  .. 4159
//  sSv  [64]      : 4160  .. 4223
//  sC   [32*32*3] : 4224  .. 7295
//  sT   [64*32*3] : 7296  .. 13439
#define SMEM_FLOATS 13440

__global__ __launch_bounds__(256, 3)
void surf_loss_kernel(const float* __restrict__ ctrl_pred,
                      const float* __restrict__ ctrl_gt,
                      const float* __restrict__ mask,
                      const float* __restrict__ xyz) {
    extern __shared__ float sm[];
    float* sBu  = sm;
    float* sBvT = sm + 2048;
    float* sSu  = sm + 4096;
    float* sSv  = sm + 4160;
    float* sC   = sm + 4224;
    float* sT   = sm + 7296;

    __shared__ int s_mu, s_mv;
    __shared__ float rs[8], rc[8], rm[8];

    const int b    = blockIdx.x;
    const int tid  = threadIdx.x;
    const int lane = tid & 31;
    const int warp = tid >> 5;

    const float* mk = mask + (size_t)b * (NM * NM);

    // ---- ragged sizes: mu = #rows with any mask>0, mv = #cols (clamped >= 4) ----
    if (warp == 0) {
        bool flag = false;
#pragma unroll 4
        for (int j = 0; j < NM; j++) flag |= (mk[lane * NM + j] > 0.0f);
        unsigned bal = __ballot_sync(0xffffffffu, flag);
        if (lane == 0) s_mu = max(__popc(bal), DEG + 1);
    } else if (warp == 1) {
        bool flag = false;
#pragma unroll 4
        for (int i = 0; i < NM; i++) flag |= (mk[i * NM + lane] > 0.0f);
        unsigned bal = __ballot_sync(0xffffffffu, flag);
        if (lane == 0) s_mv = max(__popc(bal), DEG + 1);
    }

    // ---- masked control MSE partials + stage ctrl_pred into smem ----
    const float* cp = ctrl_pred + (size_t)b * (NM * NM * 3);
    const float* cg = ctrl_gt   + (size_t)b * (NM * NM * 3);
    float lc = 0.0f, lm = 0.0f;
#pragma unroll
    for (int c = tid; c < NM * NM; c += 256) {
        float mval = mk[c];
        float p0 = cp[c * 3 + 0], p1 = cp[c * 3 + 1], p2 = cp[c * 3 + 2];
        float d0 = p0 - cg[c * 3 + 0];
        float d1 = p1 - cg[c * 3 + 1];
        float d2 = p2 - cg[c * 3 + 2];
        lc += (d0 * d0 + d1 * d1 + d2 * d2) * mval;
        lm += mval;
        sC[c * 3 + 0] = p0; sC[c * 3 + 1] = p1; sC[c * 3 + 2] = p2;
    }
    __syncthreads();

    const int mu = s_mu, mv = s_mv;
    const int miu = mu - 4, miv = mv - 4;

    // ---- load basis tables into smem ----
    {
        const float* tb  = &g_tab [miu][0][0];
        const float* tbt = &g_tabT[miv][0][0];
#pragma unroll
        for (int x = tid; x < 2048; x += 256) {
            sBu [x] = tb [x];
            sBvT[x] = tbt[x];
        }
        if (tid < 64) {
            sSu[tid] = g_sum[miu][tid];
            sSv[tid] = g_sum[miv][tid];
        }
    }
    __syncthreads();

    // ---- stage 1: T[u][j][d] = sum_{i<mu} Bu[u][i] * C[i][j][d]  (only j<mv needed) ----
    {
        const int np = NU * mv;
        for (int p = tid; p < np; p += 256) {
            int u = p / mv;
            int j = p - u * mv;
            const float* bu = &sBu[u * NM];
            float a0 = 0.0f, a1 = 0.0f, a2 = 0.0f;
            const float* cc = &sC[j * 3];
            for (int i = 0; i < mu; i++) {
                float w = bu[i];
                a0 += w * cc[i * 96 + 0];
                a1 += w * cc[i * 96 + 1];
                a2 += w * cc[i * 96 + 2];
            }
            float* t = &sT[(u * NM + j) * 3];
            t[0] = a0; t[1] = a1; t[2] = a2;
        }
    }
    __syncthreads();

    // ---- stage 2: surface eval + MSE. warp w handles u = w, w+8, ... ; lane handles v=lane, lane+32 ----
    float ls = 0.0f;
    bool  bad = false;
    const float* xb = xyz + (size_t)b * (NU * NU * 3);

    for (int u = warp; u < NU; u += 8) {
        float n00 = 0.f, n01 = 0.f, n02 = 0.f;
        float n10 = 0.f, n11 = 0.f, n12 = 0.f;
        const float* tr = &sT[u * (NM * 3)];
        for (int j = 0; j < mv; j++) {
            float t0 = tr[j * 3 + 0];
            float t1 = tr[j * 3 + 1];
            float t2 = tr[j * 3 + 2];
            float b0 = sBvT[j * NU + lane];
            float b1 = sBvT[j * NU + lane + 32];
            n00 += b0 * t0; n01 += b0 * t1; n02 += b0 * t2;
            n10 += b1 * t0; n11 += b1 * t1; n12 += b1 * t2;
        }
        float suv = sSu[u];
        float den0 = suv * sSv[lane];
        float den1 = suv * sSv[lane + 32];
        float r0 = 1.0f / den0;
        float r1 = 1.0f / den1;

        const float* x0 = xb + ((size_t)u * NU + lane) * 3;
        const float* x1 = xb + ((size_t)u * NU + lane + 32) * 3;

        float s, e;
        s = n00 * r0; bad |= !isfinite(s); e = s - x0[0]; ls += e * e;
        s = n01 * r0; bad |= !isfinite(s); e = s - x0[1]; ls += e * e;
        s = n02 * r0; bad |= !isfinite(s); e = s - x0[2]; ls += e * e;
        s = n10 * r1; bad |= !isfinite(s); e = s - x1[0]; ls += e * e;
        s = n11 * r1; bad |= !isfinite(s); e = s - x1[1]; ls += e * e;
        s = n12 * r1; bad |= !isfinite(s); e = s - x1[2]; ls += e * e;
    }

    // ---- block reduction ----
#pragma unroll
    for (int o = 16; o > 0; o >>= 1) {
        ls += __shfl_down_sync(0xffffffffu, ls, o);
        lc += __shfl_down_sync(0xffffffffu, lc, o);
        lm += __shfl_down_sync(0xffffffffu, lm, o);
    }
    if (lane == 0) { rs[warp] = ls; rc[warp] = lc; rm[warp] = lm; }
    int blockbad = __syncthreads_or(bad ? 1 : 0);
    if (tid == 0) {
        float S = 0.f, C = 0.f, M = 0.f;
#pragma unroll
        for (int i = 0; i < 8; i++) { S += rs[i]; C += rc[i]; M += rm[i]; }
        atomicAdd(&g_acc_surf, (double)S);
        atomicAdd(&g_acc_ctrl, (double)C);
        atomicAdd(&g_acc_mask, (double)M);
        if (blockbad) g_bad = 1;
    }
}

// ---------------- finalize ----------------
__global__ void finalize_kernel(float* __restrict__ out) {
    double msum = g_acc_mask * 3.0;
    double denom = msum > 1.0 ? msum : 1.0;
    double loss_ctrl = g_acc_ctrl / denom;
    double loss_surf = g_acc_surf / (double)((long long)BATCH * NU * NU * 3);
    float lc = (float)loss_ctrl;
    float lsf = (float)loss_surf;
    out[0] = lc + lsf;                      // total (pre nan-guard, W=1)
    out[1] = lc;                            // loss_ctrl
    out[2] = g_bad ? 1e6f : lsf;            // surf_mse (guarded)
}

extern "C" void kernel_launch(void* const* d_in, const int* in_sizes, int n_in,
                              void* d_out, int out_size) {
    const float* ctrl_pred = (const float*)d_in[0];   // (B,32,32,3)
    const float* ctrl_gt   = (const float*)d_in[1];   // (B,32,32,3)
    const float* mask      = (const float*)d_in[2];   // (B,32,32)
    const float* xyz       = (const float*)d_in[3];   // (B,64,64,3)
    float* out = (float*)d_out;

    size_t smem_bytes = SMEM_FLOATS * sizeof(float);  // 53.76 KB
    cudaFuncSetAttribute(surf_loss_kernel,
                         cudaFuncAttributeMaxDynamicSharedMemorySize,
                         (int)smem_bytes);

    build_tables_kernel<<<NBASIS, NU>>>();
    surf_loss_kernel<<<BATCH, 256, smem_bytes>>>(ctrl_pred, ctrl_gt, mask, xyz);
    finalize_kernel<<<1, 1>>>(out);
}

// round 4
// speedup vs baseline: 2.4248x; 2.4248x over previous
#include <cuda_runtime.h>
#include <cstdint>
#include <math.h>

#define DEG 3
#define NM 32          // MU_MAX = MV_MAX
#define NU 64          // OUT_U = OUT_V
#define BATCH 1024
#define EPSI 1e-5f

// per-block partials: x = surf-sq-err sum, y = ctrl-sq-err sum, z = mask sum
__device__ float4 g_part[BATCH];

// clamped open-uniform knot, n_valid = m ctrl pts (matches reference padding)
__device__ __forceinline__ float kvf(int k, int m) {
    if (k <= DEG) return 0.0f;
    if (k >= m)   return 1.0f;
    return (float)k / (float)(m + DEG);
}

// ---------------- main kernel: one block per batch sample ----------------
// smem (floats):
//  sC4   float4[32*32]  : 0      (16 KB)
//  sTx   float[64*32]   : 4096   (8 KB)
//  sTy   float[64*32]   : 6144
//  sTz   float[64*32]   : 8192
//  wU4   float4[64]     : 10240
//  wV4   float4[64]     : 10496
//  invSu float[64]      : 10752
//  invSv float[64]      : 10816
//  baseU int[64]        : 10880
//  baseV int[64]        : 10944
//  total 11008 floats = 44032 B
#define SMEM_FLOATS 11008

__global__ __launch_bounds__(256, 4)
void surf_loss_kernel(const float* __restrict__ ctrl_pred,
                      const float* __restrict__ ctrl_gt,
                      const float* __restrict__ mask,
                      const float* __restrict__ xyz) {
    extern __shared__ float sm[];
    float4* sC4   = (float4*)sm;
    float*  sTx   = sm + 4096;
    float*  sTy   = sm + 6144;
    float*  sTz   = sm + 8192;
    float4* wU4   = (float4*)(sm + 10240);
    float4* wV4   = (float4*)(sm + 10496);
    float*  invSu = sm + 10752;
    float*  invSv = sm + 10816;
    int*    baseU = (int*)(sm + 10880);
    int*    baseV = (int*)(sm + 10944);

    __shared__ int s_mu, s_mv;
    __shared__ float rS[8], rC[8];

    const int b    = blockIdx.x;
    const int tid  = threadIdx.x;
    const int lane = tid & 31;
    const int warp = tid >> 5;

    // ---- ragged sizes from mask row 0 / col 0 (mask is an outer product) ----
    const float* mk = mask + (size_t)b * (NM * NM);
    if (warp == 0) {
        unsigned bmv = __ballot_sync(0xffffffffu, mk[lane] > 0.0f);        // row 0 -> mv
        unsigned bmu = __ballot_sync(0xffffffffu, mk[lane * NM] > 0.0f);   // col 0 -> mu
        if (lane == 0) {
            s_mu = max(__popc(bmu), DEG + 1);
            s_mv = max(__popc(bmv), DEG + 1);
        }
    }
    __syncthreads();
    const int mu = s_mu, mv = s_mv;

    // ---- masked control MSE + stage ctrl_pred into smem (float4) ----
    const float* cp = ctrl_pred + (size_t)b * (NM * NM * 3);
    const float* cg = ctrl_gt   + (size_t)b * (NM * NM * 3);
    float lc = 0.0f;
#pragma unroll
    for (int c = tid; c < NM * NM; c += 256) {
        int i = c >> 5, j = c & 31;
        float p0 = cp[c * 3 + 0], p1 = cp[c * 3 + 1], p2 = cp[c * 3 + 2];
        float d0 = p0 - cg[c * 3 + 0];
        float d1 = p1 - cg[c * 3 + 1];
        float d2 = p2 - cg[c * 3 + 2];
        if (i < mu && j < mv) lc += d0 * d0 + d1 * d1 + d2 * d2;
        sC4[c] = make_float4(p0, p1, p2, 0.0f);
    }

    // ---- local de Boor: 4 nonzero basis weights per sample point ----
    if (tid < 128) {
        int dim = tid >> 6, g = tid & 63;
        int m = dim ? mv : mu;
        float x = EPSI + ((1.0f - 2.0f * EPSI) / 63.0f) * (float)g;
        int s = (int)(x * (float)(m + DEG));
        s = max(s, DEG); s = min(s, m - 1);
        while (s < m - 1 && x >= kvf(s + 1, m)) s++;
        while (s > DEG && x < kvf(s, m)) s--;
        float N[4]; N[0] = 1.0f; N[1] = N[2] = N[3] = 0.0f;
        float left[4], right[4];
#pragma unroll
        for (int d = 1; d <= DEG; d++) {
            left[d]  = x - kvf(s + 1 - d, m);
            right[d] = kvf(s + d, m) - x;
            float saved = 0.0f;
#pragma unroll
            for (int r = 0; r < d; r++) {
                float tmp = N[r] / (right[r + 1] + left[d - r]);
                N[r] = saved + right[r + 1] * tmp;
                saved = left[d - r] * tmp;
            }
            N[d] = saved;
        }
        float inv = 1.0f / (N[0] + N[1] + N[2] + N[3]);  // partition-of-unity denom
        if (dim == 0) {
            wU4[g] = make_float4(N[0], N[1], N[2], N[3]);
            invSu[g] = inv; baseU[g] = s - DEG;
        } else {
            wV4[g] = make_float4(N[0], N[1], N[2], N[3]);
            invSv[g] = inv; baseV[g] = s - DEG;
        }
    }
    __syncthreads();

    // ---- stage 1: T[u][j] = sum of 4 weighted ctrl rows. warp=u-group, lane=j ----
    if (lane < mv) {
#pragma unroll
        for (int u = warp; u < NU; u += 8) {
            float4 w = wU4[u];
            const float4* cc = &sC4[baseU[u] * NM + lane];
            float4 c0 = cc[0], c1 = cc[NM], c2 = cc[2 * NM], c3 = cc[3 * NM];
            sTx[u * NM + lane] = w.x * c0.x + w.y * c1.x + w.z * c2.x + w.w * c3.x;
            sTy[u * NM + lane] = w.x * c0.y + w.y * c1.y + w.z * c2.y + w.w * c3.y;
            sTz[u * NM + lane] = w.x * c0.z + w.y * c1.z + w.z * c2.z + w.w * c3.z;
        }
    }
    __syncthreads();

    // ---- stage 2: surface eval (4 sparse j-terms) + MSE ----
    float ls = 0.0f;
    {
        float4 w0 = wV4[lane],       w1 = wV4[lane + 32];
        int    j0 = baseV[lane],     j1 = baseV[lane + 32];
        float iv0 = invSv[lane],    iv1 = invSv[lane + 32];
        const float* xb = xyz + (size_t)b * (NU * NU * 3);
#pragma unroll 2
        for (int u = warp; u < NU; u += 8) {
            const float* tx = &sTx[u * NM];
            const float* ty = &sTy[u * NM];
            const float* tz = &sTz[u * NM];
            float n00 = w0.x * tx[j0] + w0.y * tx[j0 + 1] + w0.z * tx[j0 + 2] + w0.w * tx[j0 + 3];
            float n01 = w0.x * ty[j0] + w0.y * ty[j0 + 1] + w0.z * ty[j0 + 2] + w0.w * ty[j0 + 3];
            float n02 = w0.x * tz[j0] + w0.y * tz[j0 + 1] + w0.z * tz[j0 + 2] + w0.w * tz[j0 + 3];
            float n10 = w1.x * tx[j1] + w1.y * tx[j1 + 1] + w1.z * tx[j1 + 2] + w1.w * tx[j1 + 3];
            float n11 = w1.x * ty[j1] + w1.y * ty[j1 + 1] + w1.z * ty[j1 + 2] + w1.w * ty[j1 + 3];
            float n12 = w1.x * tz[j1] + w1.y * tz[j1 + 1] + w1.z * tz[j1 + 2] + w1.w * tz[j1 + 3];
            float iu = invSu[u];
            float r0 = iu * iv0;
            float r1 = iu * iv1;
            const float* x0 = xb + (size_t)(u * NU + lane) * 3;
            const float* x1 = x0 + 96;  // +32 v positions
            float e;
            e = n00 * r0 - x0[0]; ls += e * e;
            e = n01 * r0 - x0[1]; ls += e * e;
            e = n02 * r0 - x0[2]; ls += e * e;
            e = n10 * r1 - x1[0]; ls += e * e;
            e = n11 * r1 - x1[1]; ls += e * e;
            e = n12 * r1 - x1[2]; ls += e * e;
            // NaN/Inf in surf propagates into ls; guard evaluated in finalize
        }
    }

    // ---- block reduction, write partial (no atomics, no init needed) ----
#pragma unroll
    for (int o = 16; o > 0; o >>= 1) {
        ls += __shfl_down_sync(0xffffffffu, ls, o);
        lc += __shfl_down_sync(0xffffffffu, lc, o);
    }
    if (lane == 0) { rS[warp] = ls; rC[warp] = lc; }
    __syncthreads();
    if (tid == 0) {
        float S = 0.0f, C = 0.0f;
#pragma unroll
        for (int i = 0; i < 8; i++) { S += rS[i]; C += rC[i]; }
        g_part[b] = make_float4(S, C, (float)(mu * mv), 0.0f);
    }
}

// ---------------- finalize: reduce 1024 block partials ----------------
__global__ void finalize_kernel(float* __restrict__ out) {
    const int tid = threadIdx.x;
    const int lane = tid & 31, warp = tid >> 5;
    __shared__ double dS[8], dC[8], dM[8];
    double s = 0.0, c = 0.0, m = 0.0;
#pragma unroll
    for (int i = tid; i < BATCH; i += 256) {
        float4 p = g_part[i];
        s += (double)p.x; c += (double)p.y; m += (double)p.z;
    }
#pragma unroll
    for (int o = 16; o > 0; o >>= 1) {
        s += __shfl_down_sync(0xffffffffu, s, o);
        c += __shfl_down_sync(0xffffffffu, c, o);
        m += __shfl_down_sync(0xffffffffu, m, o);
    }
    if (lane == 0) { dS[warp] = s; dC[warp] = c; dM[warp] = m; }
    __syncthreads();
    if (tid == 0) {
        double S = 0.0, C = 0.0, M = 0.0;
#pragma unroll
        for (int i = 0; i < 8; i++) { S += dS[i]; C += dC[i]; M += dM[i]; }
        double denom = M * 3.0; if (denom < 1.0) denom = 1.0;
        double loss_ctrl = C / denom;
        double loss_surf = S / (double)((long long)BATCH * NU * NU * 3);
        float lcf = (float)loss_ctrl;
        float lsf = (float)loss_surf;
        out[0] = lcf + lsf;                 // total (pre nan-guard, W=1)
        out[1] = lcf;                       // loss_ctrl
        // bad iff surf had NaN/Inf -> propagated into S -> lsf NaN/Inf
        unsigned ub = __float_as_uint(lsf);
        bool bad = ((ub & 0x7f800000u) == 0x7f800000u);
        out[2] = bad ? 1e6f : lsf;          // surf_mse (guarded)
    }
}

extern "C" void kernel_launch(void* const* d_in, const int* in_sizes, int n_in,
                              void* d_out, int out_size) {
    const float* ctrl_pred = (const float*)d_in[0];   // (B,32,32,3)
    const float* ctrl_gt   = (const float*)d_in[1];   // (B,32,32,3)
    const float* mask      = (const float*)d_in[2];   // (B,32,32)
    const float* xyz       = (const float*)d_in[3];   // (B,64,64,3)
    float* out = (float*)d_out;

    size_t smem_bytes = SMEM_FLOATS * sizeof(float);  // 44032 B
    cudaFuncSetAttribute(surf_loss_kernel,
                         cudaFuncAttributeMaxDynamicSharedMemorySize,
                         (int)smem_bytes);

    surf_loss_kernel<<<BATCH, 256, smem_bytes>>>(ctrl_pred, ctrl_gt, mask, xyz);
    finalize_kernel<<<1, 256>>>(out);
}

// round 5
// speedup vs baseline: 2.4816x; 1.0234x over previous
#include <cuda_runtime.h>
#include <cstdint>
#include <math.h>

#define DEG 3
#define NM 32          // MU_MAX = MV_MAX
#define NU 64          // OUT_U = OUT_V
#define BATCH 1024
#define EPSI 1e-5f

// per-block partials: x = surf-sq-err sum, y = ctrl-sq-err sum, z = mask sum
__device__ float4 g_part[BATCH];
__device__ unsigned g_count = 0;   // last-block counter; reset by last block each launch

// clamped open-uniform knot, n_valid = m ctrl pts (matches reference padding)
__device__ __forceinline__ float kvf(int k, int m) {
    if (k <= DEG) return 0.0f;
    if (k >= m)   return 1.0f;
    return (float)k / (float)(m + DEG);
}

// ---------------- main kernel: one block per batch sample ----------------
// smem (floats), packed layout:
//  sCf   float[3072]    : 0       ctrl_pred packed xyz (12 KB)
//  sTx   float[64*32]   : 3072
//  sTy   float[64*32]   : 5120
//  sTz   float[64*32]   : 7168
//  wU4   float4[64]     : 9216
//  wV4   float4[64]     : 9472
//  invSu float[64]      : 9728
//  invSv float[64]      : 9792
//  baseU int[64]        : 9856
//  baseV int[64]        : 9920
//  total 9984 floats = 39936 B
#define SMEM_FLOATS 9984

__global__ __launch_bounds__(256, 4)
void surf_loss_kernel(const float* __restrict__ ctrl_pred,
                      const float* __restrict__ ctrl_gt,
                      const float* __restrict__ mask,
                      const float* __restrict__ xyz,
                      float* __restrict__ out) {
    extern __shared__ float sm[];
    float*  sCf   = sm;
    float*  sTx   = sm + 3072;
    float*  sTy   = sm + 5120;
    float*  sTz   = sm + 7168;
    float4* wU4   = (float4*)(sm + 9216);
    float4* wV4   = (float4*)(sm + 9472);
    float*  invSu = sm + 9728;
    float*  invSv = sm + 9792;
    int*    baseU = (int*)(sm + 9856);
    int*    baseV = (int*)(sm + 9920);

    __shared__ float rS[8], rC[8];
    __shared__ int s_last;

    const int b    = blockIdx.x;
    const int tid  = threadIdx.x;
    const int lane = tid & 31;
    const int warp = tid >> 5;

    // ---- ragged sizes: every warp computes them (no barrier needed) ----
    const float* mk = mask + (size_t)b * (NM * NM);
    unsigned bmv = __ballot_sync(0xffffffffu, mk[lane] > 0.0f);        // row 0 -> mv
    unsigned bmu = __ballot_sync(0xffffffffu, mk[lane * NM] > 0.0f);   // col 0 -> mu
    const int mu = max(__popc(bmu), DEG + 1);
    const int mv = max(__popc(bmv), DEG + 1);

    // ---- masked control MSE + stage ctrl_pred into smem, all via float4 ----
    const float4* cp4 = (const float4*)(ctrl_pred + (size_t)b * (NM * NM * 3));
    const float4* cg4 = (const float4*)(ctrl_gt   + (size_t)b * (NM * NM * 3));
    float4* sC4w = (float4*)sCf;
    float lc = 0.0f;
#pragma unroll
    for (int k = tid; k < 768; k += 256) {       // 768 float4 = 3072 floats
        float4 p = cp4[k];
        float4 g = cg4[k];
        sC4w[k] = p;
        float d0 = p.x - g.x, d1 = p.y - g.y, d2 = p.z - g.z, d3 = p.w - g.w;
        float sq[4] = { d0 * d0, d1 * d1, d2 * d2, d3 * d3 };
        int e = 4 * k;
#pragma unroll
        for (int t = 0; t < 4; t++) {
            int c = (e + t) / 3;                 // ctrl point index
            int i = c >> 5, j = c & 31;
            if (i < mu && j < mv) lc += sq[t];
        }
    }

    // ---- local de Boor: 4 nonzero basis weights per sample point ----
    if (tid < 128) {
        int dim = tid >> 6, g = tid & 63;
        int m = dim ? mv : mu;
        float x = EPSI + ((1.0f - 2.0f * EPSI) / 63.0f) * (float)g;
        int s = (int)(x * (float)(m + DEG));
        s = max(s, DEG); s = min(s, m - 1);
        while (s < m - 1 && x >= kvf(s + 1, m)) s++;
        while (s > DEG && x < kvf(s, m)) s--;
        float N[4]; N[0] = 1.0f; N[1] = N[2] = N[3] = 0.0f;
        float left[4], right[4];
#pragma unroll
        for (int d = 1; d <= DEG; d++) {
            left[d]  = x - kvf(s + 1 - d, m);
            right[d] = kvf(s + d, m) - x;
            float saved = 0.0f;
#pragma unroll
            for (int r = 0; r < d; r++) {
                float tmp = N[r] / (right[r + 1] + left[d - r]);
                N[r] = saved + right[r + 1] * tmp;
                saved = left[d - r] * tmp;
            }
            N[d] = saved;
        }
        float inv = 1.0f / (N[0] + N[1] + N[2] + N[3]);  // partition-of-unity denom
        if (dim == 0) {
            wU4[g] = make_float4(N[0], N[1], N[2], N[3]);
            invSu[g] = inv; baseU[g] = s - DEG;
        } else {
            wV4[g] = make_float4(N[0], N[1], N[2], N[3]);
            invSv[g] = inv; baseV[g] = s - DEG;
        }
    }
    __syncthreads();

    // ---- stage 1: T[u][j] = sum of 4 weighted ctrl rows. warp=u-group, lane=j ----
    if (lane < mv) {
#pragma unroll
        for (int u = warp; u < NU; u += 8) {
            float4 w = wU4[u];
            const float* cc = &sCf[(baseU[u] * NM + lane) * 3];
            // bank = (3*lane + d) mod 32, gcd(3,32)=1 -> conflict-free
            float ax = w.x * cc[0]  + w.y * cc[96]  + w.z * cc[192]  + w.w * cc[288];
            float ay = w.x * cc[1]  + w.y * cc[97]  + w.z * cc[193]  + w.w * cc[289];
            float az = w.x * cc[2]  + w.y * cc[98]  + w.z * cc[194]  + w.w * cc[290];
            sTx[u * NM + lane] = ax;
            sTy[u * NM + lane] = ay;
            sTz[u * NM + lane] = az;
        }
    }
    __syncthreads();

    // ---- stage 2: surface eval (4 sparse j-terms) + MSE ----
    float ls = 0.0f;
    {
        float4 w0 = wV4[lane],       w1 = wV4[lane + 32];
        int    j0 = baseV[lane],     j1 = baseV[lane + 32];
        float iv0 = invSv[lane],    iv1 = invSv[lane + 32];
        const float* xb = xyz + (size_t)b * (NU * NU * 3);
#pragma unroll 2
        for (int u = warp; u < NU; u += 8) {
            const float* tx = &sTx[u * NM];
            const float* ty = &sTy[u * NM];
            const float* tz = &sTz[u * NM];
            float n00 = w0.x * tx[j0] + w0.y * tx[j0 + 1] + w0.z * tx[j0 + 2] + w0.w * tx[j0 + 3];
            float n01 = w0.x * ty[j0] + w0.y * ty[j0 + 1] + w0.z * ty[j0 + 2] + w0.w * ty[j0 + 3];
            float n02 = w0.x * tz[j0] + w0.y * tz[j0 + 1] + w0.z * tz[j0 + 2] + w0.w * tz[j0 + 3];
            float n10 = w1.x * tx[j1] + w1.y * tx[j1 + 1] + w1.z * tx[j1 + 2] + w1.w * tx[j1 + 3];
            float n11 = w1.x * ty[j1] + w1.y * ty[j1 + 1] + w1.z * ty[j1 + 2] + w1.w * ty[j1 + 3];
            float n12 = w1.x * tz[j1] + w1.y * tz[j1 + 1] + w1.z * tz[j1 + 2] + w1.w * tz[j1 + 3];
            float iu = invSu[u];
            float r0 = iu * iv0;
            float r1 = iu * iv1;
            const float* x0 = xb + (size_t)(u * NU + lane) * 3;
            const float* x1 = x0 + 96;  // +32 v positions
            float e;
            e = n00 * r0 - x0[0]; ls += e * e;
            e = n01 * r0 - x0[1]; ls += e * e;
            e = n02 * r0 - x0[2]; ls += e * e;
            e = n10 * r1 - x1[0]; ls += e * e;
            e = n11 * r1 - x1[1]; ls += e * e;
            e = n12 * r1 - x1[2]; ls += e * e;
            // NaN/Inf in surf propagates into ls; guard evaluated at the end
        }
    }

    // ---- block reduction -> per-block partial ----
#pragma unroll
    for (int o = 16; o > 0; o >>= 1) {
        ls += __shfl_down_sync(0xffffffffu, ls, o);
        lc += __shfl_down_sync(0xffffffffu, lc, o);
    }
    if (lane == 0) { rS[warp] = ls; rC[warp] = lc; }
    __syncthreads();
    if (tid == 0) {
        float S = 0.0f, C = 0.0f;
#pragma unroll
        for (int i = 0; i < 8; i++) { S += rS[i]; C += rC[i]; }
        g_part[b] = make_float4(S, C, (float)(mu * mv), 0.0f);
        __threadfence();
        unsigned t = atomicAdd(&g_count, 1u);
        s_last = (t == BATCH - 1) ? 1 : 0;
    }
    __syncthreads();

    // ---- last block: global reduction + output (fused finalize) ----
    if (s_last) {
        double s = 0.0, c = 0.0, m = 0.0;
#pragma unroll
        for (int i = tid; i < BATCH; i += 256) {
            float4 p = g_part[i];
            s += (double)p.x; c += (double)p.y; m += (double)p.z;
        }
#pragma unroll
        for (int o = 16; o > 0; o >>= 1) {
            s += __shfl_down_sync(0xffffffffu, s, o);
            c += __shfl_down_sync(0xffffffffu, c, o);
            m += __shfl_down_sync(0xffffffffu, m, o);
        }
        __shared__ double dS[8], dC[8], dM[8];
        if (lane == 0) { dS[warp] = s; dC[warp] = c; dM[warp] = m; }
        __syncthreads();
        if (tid == 0) {
            double S = 0.0, C = 0.0, M = 0.0;
#pragma unroll
            for (int i = 0; i < 8; i++) { S += dS[i]; C += dC[i]; M += dM[i]; }
            double denom = M * 3.0; if (denom < 1.0) denom = 1.0;
            double loss_ctrl = C / denom;
            double loss_surf = S / (double)((long long)BATCH * NU * NU * 3);
            float lcf = (float)loss_ctrl;
            float lsf = (float)loss_surf;
            out[0] = lcf + lsf;                 // total (pre nan-guard, W=1)
            out[1] = lcf;                       // loss_ctrl
            unsigned ub = __float_as_uint(lsf);
            bool bad = ((ub & 0x7f800000u) == 0x7f800000u);
            out[2] = bad ? 1e6f : lsf;          // surf_mse (guarded)
            g_count = 0;                        // reset for next graph replay
        }
    }
}

extern "C" void kernel_launch(void* const* d_in, const int* in_sizes, int n_in,
                              void* d_out, int out_size) {
    const float* ctrl_pred = (const float*)d_in[0];   // (B,32,32,3)
    const float* ctrl_gt   = (const float*)d_in[1];   // (B,32,32,3)
    const float* mask      = (const float*)d_in[2];   // (B,32,32)
    const float* xyz       = (const float*)d_in[3];   // (B,64,64,3)
    float* out = (float*)d_out;

    size_t smem_bytes = SMEM_FLOATS * sizeof(float);  // 39936 B
    cudaFuncSetAttribute(surf_loss_kernel,
                         cudaFuncAttributeMaxDynamicSharedMemorySize,
                         (int)smem_bytes);

    surf_loss_kernel<<<BATCH, 256, smem_bytes>>>(ctrl_pred, ctrl_gt, mask, xyz, out);
}